// round 4
// baseline (speedup 1.0000x reference)
#include <cuda_runtime.h>
#include <math.h>
#include <stdint.h>

#define Bsz  2
#define Hh   16
#define Ss   1024
#define Ee   1024
#define HD   64
#define NROWS (Bsz*Ss)   // 2048
#define BH   (Bsz*Hh)    // 32

// Scratch (device globals; no allocation allowed)
__device__ float g_Qt[BH*HD*Ss];   // [bh][d][s]
__device__ float g_Kt[BH*HD*Ss];   // [bh][d][s]
__device__ float g_V [NROWS*Ee];   // [n][e] natural
__device__ float g_A [NROWS*Ee];   // attention output, natural [n][e]

// ----------------------------------------------------------------------------
// fp32 GEMM: C = X (M x 1024) * W^T + bias.  W is [N][1024] row-major.
// MODE 0: C[n][o] natural.  MODE 1: head-transposed dst[((b*16+h)*64+d)*1024+s]
// BM=BN=128, BK=8, 256 threads, 8x8 microtile, double-buffered smem.
// ----------------------------------------------------------------------------
template<int MODE>
__global__ __launch_bounds__(256, 1)
void gemm_xwt(const float* __restrict__ Xp, const float* __restrict__ Wp,
              const float* __restrict__ bias, float* __restrict__ Cp)
{
    __shared__ float as[2][8][132];
    __shared__ float bs[2][8][132];
    const int t  = threadIdx.x;
    const int m0 = blockIdx.x * 128;
    const int n0 = blockIdx.y * 128;

    const int lrow = t >> 1;          // 0..127
    const int lcol = (t & 1) << 2;    // 0 or 4
    const float* Ag = Xp + (size_t)(m0 + lrow) * Ee + lcol;
    const float* Bg = Wp + (size_t)(n0 + lrow) * Ee + lcol;

    const int tx = t & 15;            // 0..15 -> cols tx*8..
    const int ty = t >> 4;            // 0..15 -> rows ty*8..

    float acc[8][8];
#pragma unroll
    for (int i = 0; i < 8; i++)
#pragma unroll
        for (int j = 0; j < 8; j++) acc[i][j] = 0.0f;

    float4 av = *(const float4*)Ag;
    float4 bv = *(const float4*)Bg;
    int buf = 0;
    as[0][lcol+0][lrow] = av.x; as[0][lcol+1][lrow] = av.y;
    as[0][lcol+2][lrow] = av.z; as[0][lcol+3][lrow] = av.w;
    bs[0][lcol+0][lrow] = bv.x; bs[0][lcol+1][lrow] = bv.y;
    bs[0][lcol+2][lrow] = bv.z; bs[0][lcol+3][lrow] = bv.w;
    __syncthreads();

    for (int kk = 0; kk < Ee; kk += 8) {
        if (kk + 8 < Ee) {
            av = *(const float4*)(Ag + kk + 8);
            bv = *(const float4*)(Bg + kk + 8);
        }
#pragma unroll
        for (int k = 0; k < 8; k++) {
            float a[8], b[8];
            *(float4*)&a[0] = *(const float4*)&as[buf][k][ty*8];
            *(float4*)&a[4] = *(const float4*)&as[buf][k][ty*8+4];
            *(float4*)&b[0] = *(const float4*)&bs[buf][k][tx*8];
            *(float4*)&b[4] = *(const float4*)&bs[buf][k][tx*8+4];
#pragma unroll
            for (int i = 0; i < 8; i++)
#pragma unroll
                for (int j = 0; j < 8; j++)
                    acc[i][j] += a[i] * b[j];
        }
        if (kk + 8 < Ee) {
            buf ^= 1;
            as[buf][lcol+0][lrow] = av.x; as[buf][lcol+1][lrow] = av.y;
            as[buf][lcol+2][lrow] = av.z; as[buf][lcol+3][lrow] = av.w;
            bs[buf][lcol+0][lrow] = bv.x; bs[buf][lcol+1][lrow] = bv.y;
            bs[buf][lcol+2][lrow] = bv.z; bs[buf][lcol+3][lrow] = bv.w;
            __syncthreads();
        }
    }

    // epilogue
    float bcol[8];
#pragma unroll
    for (int j = 0; j < 8; j++) bcol[j] = bias[n0 + tx*8 + j];

#pragma unroll
    for (int i = 0; i < 8; i++) {
        int n = m0 + ty*8 + i;
        if (MODE == 0) {
            float4 v0, v1;
            v0.x = acc[i][0]+bcol[0]; v0.y = acc[i][1]+bcol[1];
            v0.z = acc[i][2]+bcol[2]; v0.w = acc[i][3]+bcol[3];
            v1.x = acc[i][4]+bcol[4]; v1.y = acc[i][5]+bcol[5];
            v1.z = acc[i][6]+bcol[6]; v1.w = acc[i][7]+bcol[7];
            *(float4*)&Cp[(size_t)n*Ee + n0 + tx*8]     = v0;
            *(float4*)&Cp[(size_t)n*Ee + n0 + tx*8 + 4] = v1;
        } else {
            int b = n >> 10, s = n & 1023;
#pragma unroll
            for (int j = 0; j < 8; j++) {
                int o = n0 + tx*8 + j;
                int h = o >> 6, d = o & 63;
                Cp[((size_t)((b<<4) | h)*64 + d)*1024 + s] = acc[i][j] + bcol[j];
            }
        }
    }
}

// ----------------------------------------------------------------------------
// Fused scores + exact top-64 + softmax + A@V.
// One block = 16 queries of one (b,h). 256 threads / 8 warps.
// ----------------------------------------------------------------------------
__global__ __launch_bounds__(256, 1)
void attn_kernel(const float* __restrict__ Qt, const float* __restrict__ Kt,
                 const float* __restrict__ V,  float* __restrict__ A)
{
    extern __shared__ float sm[];
    float* ks   = sm;                      // [64][256] = 16384
    float* qs   = sm + 16384;              // [64][16]  = 1024
    float* sc   = sm + 16384 + 1024;       // [16][1024]= 16384
    float* wsh  = sm + 33792;              // [8][64]   = 512
    int*   sidx = (int*)(sm + 34304);      // [8][64]   = 512
    // total = 34816 floats = 139264 bytes

    const int t   = threadIdx.x;
    const int blk = blockIdx.x;            // BH(32) * 64 q-tiles
    const int bh  = blk >> 6;              // 0..31
    const int q0g = (blk & 63) << 4;       // query base
    const int bb  = bh >> 4;               // batch
    const int hh  = bh & 15;               // head

    // load q tile, d-major
    for (int i = t; i < 64*16; i += 256) {
        int d = i >> 4, qi = i & 15;
        qs[i] = Qt[((size_t)bh*64 + d)*1024 + q0g + qi];
    }

    const int qt = t >> 6;       // 0..3
    const int kt = t & 63;       // 0..63
    const int q0 = qt * 4, k0 = kt * 4;
    const int rr = t >> 6;
    const int s4 = (t & 63) * 4;

    for (int c = 0; c < 4; c++) {
        __syncthreads();   // prior chunk compute done; qs visible on c==0
        // load K chunk [64 d][256 s], vectorized, coalesced
#pragma unroll
        for (int p = 0; p < 16; p++) {
            int r = p*4 + rr;
            *(float4*)&ks[r*256 + s4] =
                *(const float4*)&Kt[((size_t)bh*64 + r)*1024 + c*256 + s4];
        }
        __syncthreads();

        float acc[4][4];
#pragma unroll
        for (int i = 0; i < 4; i++)
#pragma unroll
            for (int j = 0; j < 4; j++) acc[i][j] = 0.0f;

#pragma unroll 8
        for (int d = 0; d < 64; d++) {
            float4 qv = *(const float4*)&qs[d*16 + q0];
            float4 kv = *(const float4*)&ks[d*256 + k0];
            float qa[4] = {qv.x, qv.y, qv.z, qv.w};
            float kb[4] = {kv.x, kv.y, kv.z, kv.w};
#pragma unroll
            for (int i = 0; i < 4; i++)
#pragma unroll
                for (int j = 0; j < 4; j++)
                    acc[i][j] += qa[i] * kb[j];
        }
#pragma unroll
        for (int i = 0; i < 4; i++) {
            float4 v;
            v.x = acc[i][0]*0.125f; v.y = acc[i][1]*0.125f;
            v.z = acc[i][2]*0.125f; v.w = acc[i][3]*0.125f;
            *(float4*)&sc[(q0+i)*1024 + (c<<8) + k0] = v;
        }
    }
    __syncthreads();   // all scores ready

    // ---- per-warp: 2 queries each; exact top-64 by bisection on uint bits ----
    const int w    = t >> 5;
    const int lane = t & 31;
    const unsigned lmlt = (1u << lane) - 1u;

    for (int qq = 0; qq < 2; qq++) {
        const int q = 2*w + qq;

        unsigned mv[32];
#pragma unroll
        for (int j = 0; j < 32; j++) {
            unsigned u = __float_as_uint(sc[q*1024 + j*32 + lane]);
            mv[j] = (u & 0x80000000u) ? ~u : (u | 0x80000000u);
        }

        unsigned lo = 0u, hi = 0xFFFFFFFFu, thr = 0u;
        bool exact = false;
        while (hi - lo > 1u) {
            unsigned mid = lo + ((hi - lo) >> 1);
            int cgt = 0;
#pragma unroll
            for (int j = 0; j < 32; j++) cgt += (mv[j] > mid);
            cgt = __reduce_add_sync(0xFFFFFFFFu, cgt);
            if (cgt == 64) { thr = mid; exact = true; break; }
            if (cgt > 64) lo = mid; else hi = mid;
        }

        if (exact) {
            int nsel = 0;
#pragma unroll
            for (int j = 0; j < 32; j++) {
                bool p = mv[j] > thr;
                unsigned bal = __ballot_sync(0xFFFFFFFFu, p);
                if (p) sidx[w*64 + nsel + __popc(bal & lmlt)] = j*32 + lane;
                nsel += __popc(bal);
            }
        } else {
            // ties at the boundary: take all strictly greater than hi,
            // then fill with ==hi in ascending index order.
            unsigned t2 = hi;
            int nsel = 0;
#pragma unroll
            for (int j = 0; j < 32; j++) {
                bool p = mv[j] > t2;
                unsigned bal = __ballot_sync(0xFFFFFFFFu, p);
                if (p) sidx[w*64 + nsel + __popc(bal & lmlt)] = j*32 + lane;
                nsel += __popc(bal);
            }
#pragma unroll
            for (int j = 0; j < 32; j++) {
                bool p = (mv[j] == t2);
                unsigned bal = __ballot_sync(0xFFFFFFFFu, p);
                if (p) {
                    int pos = nsel + __popc(bal & lmlt);
                    if (pos < 64) sidx[w*64 + pos] = j*32 + lane;
                }
                nsel += __popc(bal);
            }
        }
        __syncwarp();

        // softmax over the 64 selected scores (2 slots per lane)
        int  i0 = sidx[w*64 + lane];
        int  i1 = sidx[w*64 + lane + 32];
        float v0 = sc[q*1024 + i0];
        float v1 = sc[q*1024 + i1];
        float mx = fmaxf(v0, v1);
#pragma unroll
        for (int o = 16; o > 0; o >>= 1) mx = fmaxf(mx, __shfl_xor_sync(0xFFFFFFFFu, mx, o));
        float e0 = __expf(v0 - mx), e1 = __expf(v1 - mx);
        float ssum = e0 + e1;
#pragma unroll
        for (int o = 16; o > 0; o >>= 1) ssum += __shfl_xor_sync(0xFFFFFFFFu, ssum, o);
        wsh[w*64 + lane]      = e0;
        wsh[w*64 + lane + 32] = e1;
        __syncwarp();

        // A@V: lane covers d = 2*lane, 2*lane+1
        float ax = 0.0f, ay = 0.0f;
        const int d0 = 2*lane;
        const size_t vbase = ((size_t)bb * 1024) * 1024 + hh*64 + d0;
#pragma unroll 4
        for (int j2 = 0; j2 < 64; j2++) {
            int   id = sidx[w*64 + j2];
            float wj = wsh[w*64 + j2];
            float2 vv = *(const float2*)&V[vbase + (size_t)id*1024];
            ax += wj * vv.x;
            ay += wj * vv.y;
        }
        float invs = 1.0f / ssum;
        float2 outv; outv.x = ax*invs; outv.y = ay*invs;
        int qg = q0g + q;
        *(float2*)&A[((size_t)bb*1024 + qg)*1024 + hh*64 + d0] = outv;
        __syncwarp();
    }
}

// ----------------------------------------------------------------------------
extern "C" void kernel_launch(void* const* d_in, const int* in_sizes, int n_in,
                              void* d_out, int out_size)
{
    const float* x  = (const float*)d_in[0];
    const float* Wq = (const float*)d_in[1];
    const float* bq = (const float*)d_in[2];
    const float* Wk = (const float*)d_in[3];
    const float* bk = (const float*)d_in[4];
    const float* Wv = (const float*)d_in[5];
    const float* bv = (const float*)d_in[6];
    const float* Wo = (const float*)d_in[7];
    const float* bo = (const float*)d_in[8];
    float* out = (float*)d_out;

    float *Qt, *Kt, *Vv, *Aa;
    cudaGetSymbolAddress((void**)&Qt, g_Qt);
    cudaGetSymbolAddress((void**)&Kt, g_Kt);
    cudaGetSymbolAddress((void**)&Vv, g_V);
    cudaGetSymbolAddress((void**)&Aa, g_A);

    const int SMEM_ATTN = 34816 * 4;
    cudaFuncSetAttribute(attn_kernel,
                         cudaFuncAttributeMaxDynamicSharedMemorySize, SMEM_ATTN);

    dim3 ggrid(NROWS/128, Ee/128);
    gemm_xwt<1><<<ggrid, 256>>>(x, Wq, bq, Qt);
    gemm_xwt<1><<<ggrid, 256>>>(x, Wk, bk, Kt);
    gemm_xwt<0><<<ggrid, 256>>>(x, Wv, bv, Vv);

    attn_kernel<<<BH*64, 256, SMEM_ATTN>>>(Qt, Kt, Vv, Aa);

    gemm_xwt<0><<<ggrid, 256>>>(Aa, Wo, bo, out);
}

// round 5
// speedup vs baseline: 1.0899x; 1.0899x over previous
#include <cuda_runtime.h>
#include <math.h>
#include <stdint.h>

typedef unsigned long long u64;

#define Bsz  2
#define Hh   16
#define Ss   1024
#define Ee   1024
#define HD   64
#define NROWS (Bsz*Ss)   // 2048
#define BH   (Bsz*Hh)    // 32

// Scratch (device globals; no allocation allowed)
__device__ float g_Qt[BH*HD*Ss];   // [bh][d][s]
__device__ float g_Kt[BH*HD*Ss];   // [bh][d][s]
__device__ float g_V [NROWS*Ee];   // [n][e] natural
__device__ float g_A [NROWS*Ee];   // attention output, natural [n][e]

__device__ __forceinline__ u64 ffma2(u64 a, u64 b, u64 c) {
    u64 d;
    asm("fma.rn.f32x2 %0, %1, %2, %3;" : "=l"(d) : "l"(a), "l"(b), "l"(c));
    return d;
}
__device__ __forceinline__ u64 dup2(float x) {
    u64 d;
    asm("mov.b64 %0, {%1, %1};" : "=l"(d) : "f"(x));
    return d;
}

// ----------------------------------------------------------------------------
// fp32 GEMM via packed f32x2 FMA: C = X (2048 x 1024) * W^T + bias.
// blockIdx.z selects one of three (W, bias, C) triples; trans_mask bit z
// selects head-transposed epilogue dst[((b*16+h)*64+d)*1024+s].
// BM=BN=128, BK=8, 256 threads, 8x8 microtile (32 FFMA2/k-step),
// A tile stored DUPLICATED in smem so a-pairs load as u64 directly.
// ----------------------------------------------------------------------------
__global__ __launch_bounds__(256, 2)
void gemm_xwt(const float* __restrict__ Xp,
              const float* __restrict__ W0, const float* __restrict__ B0, float* __restrict__ C0,
              const float* __restrict__ W1, const float* __restrict__ B1, float* __restrict__ C1,
              const float* __restrict__ W2, const float* __restrict__ B2, float* __restrict__ C2,
              int trans_mask)
{
    __shared__ __align__(16) float as[2][8][264];  // duplicated pairs
    __shared__ __align__(16) float bs[2][8][132];

    const int z = blockIdx.z;
    const float* Wp   = (z == 0) ? W0 : (z == 1) ? W1 : W2;
    const float* bias = (z == 0) ? B0 : (z == 1) ? B1 : B2;
    float*       Cp   = (z == 0) ? C0 : (z == 1) ? C1 : C2;
    const bool   tr   = (trans_mask >> z) & 1;

    const int t  = threadIdx.x;
    const int m0 = blockIdx.x * 128;
    const int n0 = blockIdx.y * 128;

    const int lrow = t >> 1;          // 0..127
    const int lcol = (t & 1) << 2;    // 0 or 4
    const float* Ag = Xp + (size_t)(m0 + lrow) * Ee + lcol;
    const float* Bg = Wp + (size_t)(n0 + lrow) * Ee + lcol;

    const int tx = t & 15;            // col group
    const int ty = t >> 4;            // row group

    u64 acc2[8][4];
#pragma unroll
    for (int i = 0; i < 8; i++)
#pragma unroll
        for (int j = 0; j < 4; j++) acc2[i][j] = 0ull;

    float4 av = *(const float4*)Ag;
    float4 bv = *(const float4*)Bg;
    int buf = 0;
    *(float2*)&as[0][lcol+0][2*lrow] = make_float2(av.x, av.x);
    *(float2*)&as[0][lcol+1][2*lrow] = make_float2(av.y, av.y);
    *(float2*)&as[0][lcol+2][2*lrow] = make_float2(av.z, av.z);
    *(float2*)&as[0][lcol+3][2*lrow] = make_float2(av.w, av.w);
    bs[0][lcol+0][lrow] = bv.x; bs[0][lcol+1][lrow] = bv.y;
    bs[0][lcol+2][lrow] = bv.z; bs[0][lcol+3][lrow] = bv.w;
    __syncthreads();

    for (int kk = 0; kk < Ee; kk += 8) {
        if (kk + 8 < Ee) {
            av = *(const float4*)(Ag + kk + 8);
            bv = *(const float4*)(Bg + kk + 8);
        }
#pragma unroll
        for (int k = 0; k < 8; k++) {
            u64 a2[8], b2[4];
            *(ulonglong2*)&a2[0] = *(const ulonglong2*)&as[buf][k][ty*16];
            *(ulonglong2*)&a2[2] = *(const ulonglong2*)&as[buf][k][ty*16 + 4];
            *(ulonglong2*)&a2[4] = *(const ulonglong2*)&as[buf][k][ty*16 + 8];
            *(ulonglong2*)&a2[6] = *(const ulonglong2*)&as[buf][k][ty*16 + 12];
            *(ulonglong2*)&b2[0] = *(const ulonglong2*)&bs[buf][k][tx*8];
            *(ulonglong2*)&b2[2] = *(const ulonglong2*)&bs[buf][k][tx*8 + 4];
#pragma unroll
            for (int i = 0; i < 8; i++)
#pragma unroll
                for (int j = 0; j < 4; j++)
                    acc2[i][j] = ffma2(a2[i], b2[j], acc2[i][j]);
        }
        if (kk + 8 < Ee) {
            buf ^= 1;
            *(float2*)&as[buf][lcol+0][2*lrow] = make_float2(av.x, av.x);
            *(float2*)&as[buf][lcol+1][2*lrow] = make_float2(av.y, av.y);
            *(float2*)&as[buf][lcol+2][2*lrow] = make_float2(av.z, av.z);
            *(float2*)&as[buf][lcol+3][2*lrow] = make_float2(av.w, av.w);
            bs[buf][lcol+0][lrow] = bv.x; bs[buf][lcol+1][lrow] = bv.y;
            bs[buf][lcol+2][lrow] = bv.z; bs[buf][lcol+3][lrow] = bv.w;
            __syncthreads();
        }
    }

    // epilogue
    float bcol[8];
#pragma unroll
    for (int j = 0; j < 8; j++) bcol[j] = bias[n0 + tx*8 + j];

#pragma unroll
    for (int i = 0; i < 8; i++) {
        int n = m0 + ty*8 + i;
        float cv[8];
#pragma unroll
        for (int jp = 0; jp < 4; jp++) {
            union { u64 u; float2 f; } cc;
            cc.u = acc2[i][jp];
            cv[2*jp]   = cc.f.x + bcol[2*jp];
            cv[2*jp+1] = cc.f.y + bcol[2*jp+1];
        }
        if (!tr) {
            float4 v0 = {cv[0], cv[1], cv[2], cv[3]};
            float4 v1 = {cv[4], cv[5], cv[6], cv[7]};
            *(float4*)&Cp[(size_t)n*Ee + n0 + tx*8]     = v0;
            *(float4*)&Cp[(size_t)n*Ee + n0 + tx*8 + 4] = v1;
        } else {
            int b = n >> 10, s = n & 1023;
#pragma unroll
            for (int j = 0; j < 8; j++) {
                int o = n0 + tx*8 + j;
                int h = o >> 6, d = o & 63;
                Cp[((size_t)((b<<4) | h)*64 + d)*1024 + s] = cv[j];
            }
        }
    }
}

// ----------------------------------------------------------------------------
// Fused scores + exact top-64 + softmax + A@V.
// One block = 32 queries of one (b,h). 512 threads / 16 warps.
// smem: ks[64][256] + qs[64][32] + sc[32][1024] + wsh[16][64] + sidx[16][64]
//     = 212992 bytes.
// ----------------------------------------------------------------------------
__global__ __launch_bounds__(512, 1)
void attn_kernel(const float* __restrict__ Qt, const float* __restrict__ Kt,
                 const float* __restrict__ V,  float* __restrict__ A)
{
    extern __shared__ __align__(16) float sm[];
    float* ks   = sm;                      // [64][256] = 16384 f
    float* qs   = sm + 16384;              // [64][32]  =  2048 f
    float* sc   = sm + 18432;              // [32][1024]= 32768 f
    float* wsh  = sm + 51200;              // [16][64]  =  1024 f
    int*   sidx = (int*)(sm + 52224);      // [16][64]  =  1024 i
    // total = 53248 f = 212992 B

    const int t   = threadIdx.x;
    const int blk = blockIdx.x;            // BH(32) * 32 q-tiles
    const int bh  = blk >> 5;              // 0..31
    const int q0g = (blk & 31) << 5;       // query base
    const int bb  = bh >> 4;
    const int hh  = bh & 15;

    // load q tile, d-major (q inner)
    for (int i = t; i < 2048; i += 512) {
        int d = i >> 5, qi = i & 31;
        qs[i] = Qt[((size_t)bh*64 + d)*1024 + q0g + qi];
    }

    const int qt = t >> 6;                 // 0..7
    const int q0 = qt * 4;
    const int k0 = (t & 63) * 4;
    const int rr = t >> 6;
    const int s4 = (t & 63) * 4;

    for (int c = 0; c < 4; c++) {
        __syncthreads();   // prior chunk consumed; qs visible on c==0
#pragma unroll
        for (int p = 0; p < 8; p++) {
            int r = p*8 + rr;
            *(float4*)&ks[r*256 + s4] =
                *(const float4*)&Kt[((size_t)bh*64 + r)*1024 + c*256 + s4];
        }
        __syncthreads();

        u64 acc2[4][2];
#pragma unroll
        for (int i = 0; i < 4; i++) { acc2[i][0] = 0ull; acc2[i][1] = 0ull; }

#pragma unroll 4
        for (int d = 0; d < 64; d++) {
            float4 qv = *(const float4*)&qs[d*32 + q0];
            ulonglong2 kv = *(const ulonglong2*)&ks[d*256 + k0];
            u64 a0 = dup2(qv.x), a1 = dup2(qv.y), a2 = dup2(qv.z), a3 = dup2(qv.w);
            acc2[0][0] = ffma2(a0, kv.x, acc2[0][0]);
            acc2[0][1] = ffma2(a0, kv.y, acc2[0][1]);
            acc2[1][0] = ffma2(a1, kv.x, acc2[1][0]);
            acc2[1][1] = ffma2(a1, kv.y, acc2[1][1]);
            acc2[2][0] = ffma2(a2, kv.x, acc2[2][0]);
            acc2[2][1] = ffma2(a2, kv.y, acc2[2][1]);
            acc2[3][0] = ffma2(a3, kv.x, acc2[3][0]);
            acc2[3][1] = ffma2(a3, kv.y, acc2[3][1]);
        }
#pragma unroll
        for (int i = 0; i < 4; i++) {
            union { u64 u; float2 f; } c0, c1;
            c0.u = acc2[i][0]; c1.u = acc2[i][1];
            float4 v = {c0.f.x*0.125f, c0.f.y*0.125f, c1.f.x*0.125f, c1.f.y*0.125f};
            *(float4*)&sc[(q0+i)*1024 + (c<<8) + k0] = v;
        }
    }
    __syncthreads();   // all scores ready

    // ---- per-warp: 2 queries each; exact top-64 via bisection on uint bits ----
    const int w    = t >> 5;               // 0..15
    const int lane = t & 31;
    const unsigned lmlt = (1u << lane) - 1u;

    for (int qq = 0; qq < 2; qq++) {
        const int q = 2*w + qq;

        unsigned mv[32];
        unsigned mn = 0xFFFFFFFFu, mx = 0u;
#pragma unroll
        for (int j = 0; j < 32; j++) {
            unsigned u = __float_as_uint(sc[q*1024 + j*32 + lane]);
            unsigned m = (u & 0x80000000u) ? ~u : (u | 0x80000000u);
            mv[j] = m;
            mn = min(mn, m); mx = max(mx, m);
        }
        mn = __reduce_min_sync(0xFFFFFFFFu, mn);
        mx = __reduce_max_sync(0xFFFFFFFFu, mx);

        unsigned lo = mn, hi = mx, thr = 0u;
        bool exact = false;
        while (hi - lo > 1u) {
            unsigned mid = lo + ((hi - lo) >> 1);
            int cgt = 0;
#pragma unroll
            for (int j = 0; j < 32; j++) cgt += (mv[j] > mid);
            cgt = __reduce_add_sync(0xFFFFFFFFu, cgt);
            if (cgt == 64) { thr = mid; exact = true; break; }
            if (cgt > 64) lo = mid; else hi = mid;
        }

        if (exact) {
            int nsel = 0;
#pragma unroll
            for (int j = 0; j < 32; j++) {
                bool p = mv[j] > thr;
                unsigned bal = __ballot_sync(0xFFFFFFFFu, p);
                if (p) sidx[w*64 + nsel + __popc(bal & lmlt)] = j*32 + lane;
                nsel += __popc(bal);
            }
        } else {
            // boundary ties: strictly greater than hi, then fill with ==hi
            unsigned t2 = hi;
            int nsel = 0;
#pragma unroll
            for (int j = 0; j < 32; j++) {
                bool p = mv[j] > t2;
                unsigned bal = __ballot_sync(0xFFFFFFFFu, p);
                if (p) sidx[w*64 + nsel + __popc(bal & lmlt)] = j*32 + lane;
                nsel += __popc(bal);
            }
#pragma unroll
            for (int j = 0; j < 32; j++) {
                bool p = (mv[j] == t2);
                unsigned bal = __ballot_sync(0xFFFFFFFFu, p);
                if (p) {
                    int pos = nsel + __popc(bal & lmlt);
                    if (pos < 64) sidx[w*64 + pos] = j*32 + lane;
                }
                nsel += __popc(bal);
            }
        }
        __syncwarp();

        // softmax over the 64 selected (2 slots/lane)
        int  i0 = sidx[w*64 + lane];
        int  i1 = sidx[w*64 + lane + 32];
        float v0 = sc[q*1024 + i0];
        float v1 = sc[q*1024 + i1];
        float mxf = fmaxf(v0, v1);
#pragma unroll
        for (int o = 16; o > 0; o >>= 1) mxf = fmaxf(mxf, __shfl_xor_sync(0xFFFFFFFFu, mxf, o));
        float e0 = __expf(v0 - mxf), e1 = __expf(v1 - mxf);
        float ssum = e0 + e1;
#pragma unroll
        for (int o = 16; o > 0; o >>= 1) ssum += __shfl_xor_sync(0xFFFFFFFFu, ssum, o);
        wsh[w*64 + lane]      = e0;
        wsh[w*64 + lane + 32] = e1;
        __syncwarp();

        // A@V: lane covers d = 2*lane, 2*lane+1
        float ax = 0.0f, ay = 0.0f;
        const int d0 = 2*lane;
        const size_t vbase = ((size_t)bb * 1024) * 1024 + hh*64 + d0;
#pragma unroll 4
        for (int j2 = 0; j2 < 64; j2++) {
            int   id = sidx[w*64 + j2];
            float wj = wsh[w*64 + j2];
            float2 vv = *(const float2*)&V[vbase + (size_t)id*1024];
            ax += wj * vv.x;
            ay += wj * vv.y;
        }
        float invs = 1.0f / ssum;
        float2 outv; outv.x = ax*invs; outv.y = ay*invs;
        int qg = q0g + q;
        *(float2*)&A[((size_t)bb*1024 + qg)*1024 + hh*64 + d0] = outv;
        __syncwarp();
    }
}

// ----------------------------------------------------------------------------
extern "C" void kernel_launch(void* const* d_in, const int* in_sizes, int n_in,
                              void* d_out, int out_size)
{
    const float* x  = (const float*)d_in[0];
    const float* Wq = (const float*)d_in[1];
    const float* bq = (const float*)d_in[2];
    const float* Wk = (const float*)d_in[3];
    const float* bk = (const float*)d_in[4];
    const float* Wv = (const float*)d_in[5];
    const float* bv = (const float*)d_in[6];
    const float* Wo = (const float*)d_in[7];
    const float* bo = (const float*)d_in[8];
    float* out = (float*)d_out;

    float *Qt, *Kt, *Vv, *Aa;
    cudaGetSymbolAddress((void**)&Qt, g_Qt);
    cudaGetSymbolAddress((void**)&Kt, g_Kt);
    cudaGetSymbolAddress((void**)&Vv, g_V);
    cudaGetSymbolAddress((void**)&Aa, g_A);

    const int SMEM_ATTN = 53248 * 4;
    cudaFuncSetAttribute(attn_kernel,
                         cudaFuncAttributeMaxDynamicSharedMemorySize, SMEM_ATTN);

    // fused Q/K/V projections (z selects the triple; Q,K head-transposed)
    dim3 gqkv(NROWS/128, Ee/128, 3);
    gemm_xwt<<<gqkv, 256>>>(x,
                            Wq, bq, Qt,
                            Wk, bk, Kt,
                            Wv, bv, Vv, 0b011);

    attn_kernel<<<BH*32, 512, SMEM_ATTN>>>(Qt, Kt, Vv, Aa);

    // output projection
    dim3 go(NROWS/128, Ee/128, 1);
    gemm_xwt<<<go, 256>>>(Aa,
                          Wo, bo, out,
                          Wo, bo, out,
                          Wo, bo, out, 0);
}

// round 10
// speedup vs baseline: 1.3406x; 1.2300x over previous
#include <cuda_runtime.h>
#include <cuda_bf16.h>
#include <math.h>
#include <stdint.h>

typedef unsigned long long u64;

#define Bsz  2
#define Hh   16
#define Ss   1024
#define Ee   1024
#define HD   64
#define NROWS (Bsz*Ss)   // 2048
#define BH   (Bsz*Hh)    // 32

#define XSTRIDE (NROWS*Ee)   // 2097152
#define WSTRIDE (Ee*Ee)      // 1048576

// Scratch (device globals; no allocation allowed)
__device__ float g_Qt[BH*HD*Ss];   // [bh][d][s]
__device__ float g_Kt[BH*HD*Ss];   // [bh][d][s]
__device__ float g_V [NROWS*Ee];   // [n][e]
__device__ float g_A [NROWS*Ee];   // attention out [n][e]

// bf16 split planes (2 planes used)
__device__ __nv_bfloat16 g_X2[2*XSTRIDE];
__device__ __nv_bfloat16 g_A2[2*XSTRIDE];
__device__ __nv_bfloat16 g_Wv2[2*WSTRIDE];
__device__ __nv_bfloat16 g_Wo2[2*WSTRIDE];

// ---------------------------------------------------------------------------
// helpers
// ---------------------------------------------------------------------------
__device__ __forceinline__ uint32_t smem_to_u32(const void* p) {
    uint32_t a;
    asm("{ .reg .u64 t; cvta.to.shared.u64 t, %1; cvt.u32.u64 %0, t; }"
        : "=r"(a) : "l"(p));
    return a;
}
__device__ __forceinline__ u64 ffma2(u64 a, u64 b, u64 c) {
    u64 d;
    asm("fma.rn.f32x2 %0, %1, %2, %3;" : "=l"(d) : "l"(a), "l"(b), "l"(c));
    return d;
}
__device__ __forceinline__ u64 dup2(float x) {
    u64 d;
    asm("mov.b64 %0, {%1, %1};" : "=l"(d) : "f"(x));
    return d;
}
__device__ __forceinline__ void cpasync16(uint32_t s, const void* g) {
    asm volatile("cp.async.cg.shared.global [%0], [%1], 16;" :: "r"(s), "l"(g));
}
__device__ __forceinline__ void cpcommit() {
    asm volatile("cp.async.commit_group;" ::: "memory");
}
__device__ __forceinline__ void ldmx4(uint32_t* r, uint32_t addr) {
    asm volatile("ldmatrix.sync.aligned.m8n8.x4.shared.b16 {%0,%1,%2,%3}, [%4];"
                 : "=r"(r[0]), "=r"(r[1]), "=r"(r[2]), "=r"(r[3]) : "r"(addr));
}
__device__ __forceinline__ void mma16816(float* d, const uint32_t* a,
                                         uint32_t b0, uint32_t b1) {
    asm volatile("mma.sync.aligned.m16n8k16.row.col.f32.bf16.bf16.f32 "
                 "{%0,%1,%2,%3}, {%4,%5,%6,%7}, {%8,%9}, {%0,%1,%2,%3};"
                 : "+f"(d[0]), "+f"(d[1]), "+f"(d[2]), "+f"(d[3])
                 : "r"(a[0]), "r"(a[1]), "r"(a[2]), "r"(a[3]), "r"(b0), "r"(b1));
}

// ---------------------------------------------------------------------------
// fp32 -> 2x bf16 plane converter (hi + residual)
// ---------------------------------------------------------------------------
__global__ __launch_bounds__(256)
void conv2k(const float* __restrict__ src, __nv_bfloat16* __restrict__ dst,
            int n4, int pstride)
{
    int i = blockIdx.x * 256 + threadIdx.x;
    if (i >= n4) return;
    float4 a = ((const float4*)src)[i];
    float av[4] = {a.x, a.y, a.z, a.w};
    unsigned short p0[4], p1[4];
#pragma unroll
    for (int j = 0; j < 4; j++) {
        float x = av[j];
        __nv_bfloat16 h0 = __float2bfloat16(x);
        float r1 = x - __bfloat162float(h0);
        __nv_bfloat16 h1 = __float2bfloat16(r1);
        p0[j] = __bfloat16_as_ushort(h0);
        p1[j] = __bfloat16_as_ushort(h1);
    }
    ((uint2*)(dst))[i]           = *(uint2*)p0;
    ((uint2*)(dst + pstride))[i] = *(uint2*)p1;
}

// ---------------------------------------------------------------------------
// R5-exact FFMA2 fp32 GEMM (bitwise-reproducible Q/K): C = X @ W^T + bias.
// blockIdx.z selects triple; trans_mask bit z -> head-transposed epilogue.
// ---------------------------------------------------------------------------
__global__ __launch_bounds__(256, 2)
void gemm_xwt(const float* __restrict__ Xp,
              const float* __restrict__ W0, const float* __restrict__ B0, float* __restrict__ C0,
              const float* __restrict__ W1, const float* __restrict__ B1, float* __restrict__ C1,
              const float* __restrict__ W2, const float* __restrict__ B2, float* __restrict__ C2,
              int trans_mask)
{
    __shared__ __align__(16) float as[2][8][264];  // duplicated pairs
    __shared__ __align__(16) float bs[2][8][132];

    const int z = blockIdx.z;
    const float* Wp   = (z == 0) ? W0 : (z == 1) ? W1 : W2;
    const float* bias = (z == 0) ? B0 : (z == 1) ? B1 : B2;
    float*       Cp   = (z == 0) ? C0 : (z == 1) ? C1 : C2;
    const bool   tr   = (trans_mask >> z) & 1;

    const int t  = threadIdx.x;
    const int m0 = blockIdx.x * 128;
    const int n0 = blockIdx.y * 128;

    const int lrow = t >> 1;
    const int lcol = (t & 1) << 2;
    const float* Ag = Xp + (size_t)(m0 + lrow) * Ee + lcol;
    const float* Bg = Wp + (size_t)(n0 + lrow) * Ee + lcol;

    const int tx = t & 15;
    const int ty = t >> 4;

    u64 acc2[8][4];
#pragma unroll
    for (int i = 0; i < 8; i++)
#pragma unroll
        for (int j = 0; j < 4; j++) acc2[i][j] = 0ull;

    float4 av = *(const float4*)Ag;
    float4 bv = *(const float4*)Bg;
    int buf = 0;
    *(float2*)&as[0][lcol+0][2*lrow] = make_float2(av.x, av.x);
    *(float2*)&as[0][lcol+1][2*lrow] = make_float2(av.y, av.y);
    *(float2*)&as[0][lcol+2][2*lrow] = make_float2(av.z, av.z);
    *(float2*)&as[0][lcol+3][2*lrow] = make_float2(av.w, av.w);
    bs[0][lcol+0][lrow] = bv.x; bs[0][lcol+1][lrow] = bv.y;
    bs[0][lcol+2][lrow] = bv.z; bs[0][lcol+3][lrow] = bv.w;
    __syncthreads();

    for (int kk = 0; kk < Ee; kk += 8) {
        if (kk + 8 < Ee) {
            av = *(const float4*)(Ag + kk + 8);
            bv = *(const float4*)(Bg + kk + 8);
        }
#pragma unroll
        for (int k = 0; k < 8; k++) {
            u64 a2[8], b2[4];
            *(ulonglong2*)&a2[0] = *(const ulonglong2*)&as[buf][k][ty*16];
            *(ulonglong2*)&a2[2] = *(const ulonglong2*)&as[buf][k][ty*16 + 4];
            *(ulonglong2*)&a2[4] = *(const ulonglong2*)&as[buf][k][ty*16 + 8];
            *(ulonglong2*)&a2[6] = *(const ulonglong2*)&as[buf][k][ty*16 + 12];
            *(ulonglong2*)&b2[0] = *(const ulonglong2*)&bs[buf][k][tx*8];
            *(ulonglong2*)&b2[2] = *(const ulonglong2*)&bs[buf][k][tx*8 + 4];
#pragma unroll
            for (int i = 0; i < 8; i++)
#pragma unroll
                for (int j = 0; j < 4; j++)
                    acc2[i][j] = ffma2(a2[i], b2[j], acc2[i][j]);
        }
        if (kk + 8 < Ee) {
            buf ^= 1;
            *(float2*)&as[buf][lcol+0][2*lrow] = make_float2(av.x, av.x);
            *(float2*)&as[buf][lcol+1][2*lrow] = make_float2(av.y, av.y);
            *(float2*)&as[buf][lcol+2][2*lrow] = make_float2(av.z, av.z);
            *(float2*)&as[buf][lcol+3][2*lrow] = make_float2(av.w, av.w);
            bs[buf][lcol+0][lrow] = bv.x; bs[buf][lcol+1][lrow] = bv.y;
            bs[buf][lcol+2][lrow] = bv.z; bs[buf][lcol+3][lrow] = bv.w;
            __syncthreads();
        }
    }

    float bcol[8];
#pragma unroll
    for (int j = 0; j < 8; j++) bcol[j] = bias[n0 + tx*8 + j];

#pragma unroll
    for (int i = 0; i < 8; i++) {
        int n = m0 + ty*8 + i;
        float cv[8];
#pragma unroll
        for (int jp = 0; jp < 4; jp++) {
            union { u64 u; float2 f; } cc;
            cc.u = acc2[i][jp];
            cv[2*jp]   = cc.f.x + bcol[2*jp];
            cv[2*jp+1] = cc.f.y + bcol[2*jp+1];
        }
        if (!tr) {
            float4 v0 = {cv[0], cv[1], cv[2], cv[3]};
            float4 v1 = {cv[4], cv[5], cv[6], cv[7]};
            *(float4*)&Cp[(size_t)n*Ee + n0 + tx*8]     = v0;
            *(float4*)&Cp[(size_t)n*Ee + n0 + tx*8 + 4] = v1;
        } else {
            int b = n >> 10, s = n & 1023;
#pragma unroll
            for (int j = 0; j < 8; j++) {
                int o = n0 + tx*8 + j;
                int h = o >> 6, d = o & 63;
                Cp[((size_t)((b<<4) | h)*64 + d)*1024 + s] = cv[j];
            }
        }
    }
}

// ---------------------------------------------------------------------------
// bf16x2 (3-pass) HMMA GEMM for V and O: C = X @ W^T + bias, natural layout.
// 128x128 tile, BK=32, 256 thr / 8 warps (warp tile 32x64), cp.async double
// buffer, 80B-padded rows (conflict-free ldmatrix).
// passes: (0,0),(0,1),(1,0) -> rel error ~2^-18.
// ---------------------------------------------------------------------------
#define PLB3  20480            // 2 planes * 10240 bytes per operand per buffer
#define BUFB3 40960
#define SMEM_HMMA (2*BUFB3)    // 81920

__global__ __launch_bounds__(256, 1)
void gemm_hmma3(const __nv_bfloat16* __restrict__ A2, int aStride,
                const __nv_bfloat16* __restrict__ W2,
                const float* __restrict__ bias, float* __restrict__ C)
{
    extern __shared__ __align__(16) char smem[];
    const uint32_t sb = smem_to_u32(smem);

    const int t    = threadIdx.x;
    const int wid  = t >> 5;
    const int lane = t & 31;

    const int m0 = blockIdx.x * 128;
    const int n0 = blockIdx.y * 128;

    const __nv_bfloat16* gA[4];
    const __nv_bfloat16* gB[4];
    uint32_t sAo[4];
#pragma unroll
    for (int u = 0; u < 4; u++) {
        int idx = t + (u << 8);            // 0..1023
        int p   = idx >> 9;                // plane 0/1
        int rem = idx & 511;
        int r   = rem >> 2;                // row 0..127
        int c8  = rem & 3;                 // 16B group within 32 k
        gA[u] = A2 + (size_t)p * aStride + (size_t)(m0 + r) * 1024 + c8 * 8;
        gB[u] = W2 + (size_t)p * WSTRIDE + (size_t)(n0 + r) * 1024 + c8 * 8;
        sAo[u] = (uint32_t)(p * 10240 + r * 80 + c8 * 16);
    }

    auto loadbuf = [&](int bb, int kc) {
        uint32_t base = sb + bb * BUFB3;
#pragma unroll
        for (int u = 0; u < 4; u++) cpasync16(base + sAo[u], gA[u] + kc * 32);
#pragma unroll
        for (int u = 0; u < 4; u++) cpasync16(base + PLB3 + sAo[u], gB[u] + kc * 32);
        cpcommit();
    };

    const int wm32 = (wid >> 1) * 32;
    const int wn64 = (wid & 1) * 64;
    const int arow = lane & 15;
    const uint32_t c8b = ((lane >> 4) & 1) * 16;

    float acc[2][8][4];
#pragma unroll
    for (int i = 0; i < 2; i++)
#pragma unroll
        for (int j = 0; j < 8; j++)
#pragma unroll
            for (int q = 0; q < 4; q++) acc[i][j][q] = 0.0f;

    loadbuf(0, 0);

#pragma unroll 1
    for (int kc = 0; kc < 32; kc++) {
        if (kc < 31) {
            loadbuf((kc + 1) & 1, kc + 1);
            asm volatile("cp.async.wait_group 1;" ::: "memory");
        } else {
            asm volatile("cp.async.wait_group 0;" ::: "memory");
        }
        __syncthreads();

        const uint32_t bufo = sb + (kc & 1) * BUFB3;
#pragma unroll
        for (int ks = 0; ks < 2; ks++) {
            uint32_t aF[2][2][4];
            uint32_t bF[2][4][4];
#pragma unroll
            for (int p = 0; p < 2; p++)
#pragma unroll
                for (int mt = 0; mt < 2; mt++) {
                    uint32_t ad = bufo + p * 10240 +
                        (uint32_t)(wm32 + mt * 16 + arow) * 80 + ks * 32 + c8b;
                    ldmx4(aF[p][mt], ad);
                }
#pragma unroll
            for (int q = 0; q < 2; q++)
#pragma unroll
                for (int ng = 0; ng < 4; ng++) {
                    uint32_t bd = bufo + PLB3 + q * 10240 +
                        (uint32_t)(wn64 + ng * 16 + arow) * 80 + ks * 32 + c8b;
                    ldmx4(bF[q][ng], bd);
                }
            // passes (p,q): (0,0),(0,1),(1,0)
#pragma unroll
            for (int i3 = 0; i3 < 3; i3++) {
                const int p = (i3 == 2) ? 1 : 0;
                const int q = (i3 == 1) ? 1 : 0;
#pragma unroll
                for (int mt = 0; mt < 2; mt++)
#pragma unroll
                    for (int nt = 0; nt < 8; nt++) {
                        const int ng = nt >> 1, par = nt & 1;
                        mma16816(acc[mt][nt], aF[p][mt],
                                 bF[q][ng][par], bF[q][ng][par + 2]);
                    }
            }
        }
        __syncthreads();
    }

    // epilogue (natural layout)
    const int rbase = m0 + wm32 + (lane >> 2);
    const int cbase = n0 + wn64 + (lane & 3) * 2;
#pragma unroll
    for (int mt = 0; mt < 2; mt++) {
        const int r0 = rbase + mt * 16;
        const int r1 = r0 + 8;
#pragma unroll
        for (int nt = 0; nt < 8; nt++) {
            const int col = cbase + nt * 8;
            const float2 bi = *(const float2*)&bias[col];
            *(float2*)&C[(size_t)r0 * 1024 + col] =
                make_float2(acc[mt][nt][0] + bi.x, acc[mt][nt][1] + bi.y);
            *(float2*)&C[(size_t)r1 * 1024 + col] =
                make_float2(acc[mt][nt][2] + bi.x, acc[mt][nt][3] + bi.y);
        }
    }
}

// ----------------------------------------------------------------------------
// Fused scores + exact top-64 + softmax + A@V (R5-exact, bitwise identical).
// One block = 32 queries of one (b,h). 512 threads / 16 warps.
// ----------------------------------------------------------------------------
__global__ __launch_bounds__(512, 1)
void attn_kernel(const float* __restrict__ Qt, const float* __restrict__ Kt,
                 const float* __restrict__ V,  float* __restrict__ A)
{
    extern __shared__ __align__(16) float sm[];
    float* ks   = sm;                      // [64][256]
    float* qs   = sm + 16384;              // [64][32]
    float* sc   = sm + 18432;              // [32][1024]
    float* wsh  = sm + 51200;              // [16][64]
    int*   sidx = (int*)(sm + 52224);      // [16][64]

    const int t   = threadIdx.x;
    const int blk = blockIdx.x;
    const int bh  = blk >> 5;
    const int q0g = (blk & 31) << 5;
    const int bb  = bh >> 4;
    const int hh  = bh & 15;

    for (int i = t; i < 2048; i += 512) {
        int d = i >> 5, qi = i & 31;
        qs[i] = Qt[((size_t)bh*64 + d)*1024 + q0g + qi];
    }

    const int qt = t >> 6;
    const int q0 = qt * 4;
    const int k0 = (t & 63) * 4;
    const int rr = t >> 6;
    const int s4 = (t & 63) * 4;

    for (int c = 0; c < 4; c++) {
        __syncthreads();
#pragma unroll
        for (int p = 0; p < 8; p++) {
            int r = p*8 + rr;
            *(float4*)&ks[r*256 + s4] =
                *(const float4*)&Kt[((size_t)bh*64 + r)*1024 + c*256 + s4];
        }
        __syncthreads();

        u64 acc2[4][2];
#pragma unroll
        for (int i = 0; i < 4; i++) { acc2[i][0] = 0ull; acc2[i][1] = 0ull; }

#pragma unroll 4
        for (int d = 0; d < 64; d++) {
            float4 qv = *(const float4*)&qs[d*32 + q0];
            ulonglong2 kv = *(const ulonglong2*)&ks[d*256 + k0];
            u64 a0 = dup2(qv.x), a1 = dup2(qv.y), a2 = dup2(qv.z), a3 = dup2(qv.w);
            acc2[0][0] = ffma2(a0, kv.x, acc2[0][0]);
            acc2[0][1] = ffma2(a0, kv.y, acc2[0][1]);
            acc2[1][0] = ffma2(a1, kv.x, acc2[1][0]);
            acc2[1][1] = ffma2(a1, kv.y, acc2[1][1]);
            acc2[2][0] = ffma2(a2, kv.x, acc2[2][0]);
            acc2[2][1] = ffma2(a2, kv.y, acc2[2][1]);
            acc2[3][0] = ffma2(a3, kv.x, acc2[3][0]);
            acc2[3][1] = ffma2(a3, kv.y, acc2[3][1]);
        }
#pragma unroll
        for (int i = 0; i < 4; i++) {
            union { u64 u; float2 f; } c0, c1;
            c0.u = acc2[i][0]; c1.u = acc2[i][1];
            float4 v = {c0.f.x*0.125f, c0.f.y*0.125f, c1.f.x*0.125f, c1.f.y*0.125f};
            *(float4*)&sc[(q0+i)*1024 + (c<<8) + k0] = v;
        }
    }
    __syncthreads();

    const int w    = t >> 5;
    const int lane = t & 31;
    const unsigned lmlt = (1u << lane) - 1u;

    for (int qq = 0; qq < 2; qq++) {
        const int q = 2*w + qq;

        unsigned mv[32];
        unsigned mn = 0xFFFFFFFFu, mx = 0u;
#pragma unroll
        for (int j = 0; j < 32; j++) {
            unsigned u = __float_as_uint(sc[q*1024 + j*32 + lane]);
            unsigned m = (u & 0x80000000u) ? ~u : (u | 0x80000000u);
            mv[j] = m;
            mn = min(mn, m); mx = max(mx, m);
        }
        mn = __reduce_min_sync(0xFFFFFFFFu, mn);
        mx = __reduce_max_sync(0xFFFFFFFFu, mx);

        unsigned lo = mn, hi = mx, thr = 0u;
        bool exact = false;
        while (hi - lo > 1u) {
            unsigned mid = lo + ((hi - lo) >> 1);
            int cgt = 0;
#pragma unroll
            for (int j = 0; j < 32; j++) cgt += (mv[j] > mid);
            cgt = __reduce_add_sync(0xFFFFFFFFu, cgt);
            if (cgt == 64) { thr = mid; exact = true; break; }
            if (cgt > 64) lo = mid; else hi = mid;
        }

        if (exact) {
            int nsel = 0;
#pragma unroll
            for (int j = 0; j < 32; j++) {
                bool p = mv[j] > thr;
                unsigned bal = __ballot_sync(0xFFFFFFFFu, p);
                if (p) sidx[w*64 + nsel + __popc(bal & lmlt)] = j*32 + lane;
                nsel += __popc(bal);
            }
        } else {
            unsigned t2 = hi;
            int nsel = 0;
#pragma unroll
            for (int j = 0; j < 32; j++) {
                bool p = mv[j] > t2;
                unsigned bal = __ballot_sync(0xFFFFFFFFu, p);
                if (p) sidx[w*64 + nsel + __popc(bal & lmlt)] = j*32 + lane;
                nsel += __popc(bal);
            }
#pragma unroll
            for (int j = 0; j < 32; j++) {
                bool p = (mv[j] == t2);
                unsigned bal = __ballot_sync(0xFFFFFFFFu, p);
                if (p) {
                    int pos = nsel + __popc(bal & lmlt);
                    if (pos < 64) sidx[w*64 + pos] = j*32 + lane;
                }
                nsel += __popc(bal);
            }
        }
        __syncwarp();

        int  i0 = sidx[w*64 + lane];
        int  i1 = sidx[w*64 + lane + 32];
        float v0 = sc[q*1024 + i0];
        float v1 = sc[q*1024 + i1];
        float mxf = fmaxf(v0, v1);
#pragma unroll
        for (int o = 16; o > 0; o >>= 1) mxf = fmaxf(mxf, __shfl_xor_sync(0xFFFFFFFFu, mxf, o));
        float e0 = __expf(v0 - mxf), e1 = __expf(v1 - mxf);
        float ssum = e0 + e1;
#pragma unroll
        for (int o = 16; o > 0; o >>= 1) ssum += __shfl_xor_sync(0xFFFFFFFFu, ssum, o);
        wsh[w*64 + lane]      = e0;
        wsh[w*64 + lane + 32] = e1;
        __syncwarp();

        float ax = 0.0f, ay = 0.0f;
        const int d0 = 2*lane;
        const size_t vbase = ((size_t)bb * 1024) * 1024 + hh*64 + d0;
#pragma unroll 4
        for (int j2 = 0; j2 < 64; j2++) {
            int   id = sidx[w*64 + j2];
            float wj = wsh[w*64 + j2];
            float2 vv = *(const float2*)&V[vbase + (size_t)id*1024];
            ax += wj * vv.x;
            ay += wj * vv.y;
        }
        float invs = 1.0f / ssum;
        float2 outv; outv.x = ax*invs; outv.y = ay*invs;
        int qg = q0g + q;
        *(float2*)&A[((size_t)bb*1024 + qg)*1024 + hh*64 + d0] = outv;
        __syncwarp();
    }
}

// ----------------------------------------------------------------------------
extern "C" void kernel_launch(void* const* d_in, const int* in_sizes, int n_in,
                              void* d_out, int out_size)
{
    const float* x  = (const float*)d_in[0];
    const float* Wq = (const float*)d_in[1];
    const float* bq = (const float*)d_in[2];
    const float* Wk = (const float*)d_in[3];
    const float* bk = (const float*)d_in[4];
    const float* Wv = (const float*)d_in[5];
    const float* bv = (const float*)d_in[6];
    const float* Wo = (const float*)d_in[7];
    const float* bo = (const float*)d_in[8];
    float* out = (float*)d_out;

    float *Qt, *Kt, *Vv, *Aa;
    cudaGetSymbolAddress((void**)&Qt, g_Qt);
    cudaGetSymbolAddress((void**)&Kt, g_Kt);
    cudaGetSymbolAddress((void**)&Vv, g_V);
    cudaGetSymbolAddress((void**)&Aa, g_A);
    __nv_bfloat16 *X2, *A2, *Wv2, *Wo2;
    cudaGetSymbolAddress((void**)&X2,  g_X2);
    cudaGetSymbolAddress((void**)&A2,  g_A2);
    cudaGetSymbolAddress((void**)&Wv2, g_Wv2);
    cudaGetSymbolAddress((void**)&Wo2, g_Wo2);

    const int SMEM_ATTN = 53248 * 4;
    cudaFuncSetAttribute(attn_kernel,
                         cudaFuncAttributeMaxDynamicSharedMemorySize, SMEM_ATTN);
    cudaFuncSetAttribute(gemm_hmma3,
                         cudaFuncAttributeMaxDynamicSharedMemorySize, SMEM_HMMA);

    // conversions for the HMMA (flip-insensitive) paths
    conv2k<<<XSTRIDE/4/256, 256>>>(x,  X2,  XSTRIDE/4, XSTRIDE);
    conv2k<<<WSTRIDE/4/256, 256>>>(Wv, Wv2, WSTRIDE/4, WSTRIDE);
    conv2k<<<WSTRIDE/4/256, 256>>>(Wo, Wo2, WSTRIDE/4, WSTRIDE);

    // Q and K: R5-exact FFMA2 fp32 GEMM, head-transposed (bitwise-identical
    // Qt/Kt -> identical top-k flip set -> rel_err pinned at 6.92e-4)
    dim3 gqk(NROWS/128, Ee/128, 2);
    gemm_xwt<<<gqk, 256>>>(x,
                           Wq, bq, Qt,
                           Wk, bk, Kt,
                           Wk, bk, Kt, 0b11);

    // V: HMMA bf16x2
    dim3 gv(NROWS/128, Ee/128);
    gemm_hmma3<<<gv, 256, SMEM_HMMA>>>(X2, XSTRIDE, Wv2, bv, Vv);

    attn_kernel<<<BH*32, 512, SMEM_ATTN>>>(Qt, Kt, Vv, Aa);

    // O-projection: HMMA bf16x2
    conv2k<<<XSTRIDE/4/256, 256>>>(Aa, A2, XSTRIDE/4, XSTRIDE);
    gemm_hmma3<<<gv, 256, SMEM_HMMA>>>(A2, XSTRIDE, Wo2, bo, out);
}

// round 11
// speedup vs baseline: 1.4729x; 1.0987x over previous
#include <cuda_runtime.h>
#include <cuda_bf16.h>
#include <math.h>
#include <stdint.h>

typedef unsigned long long u64;

#define Bsz  2
#define Hh   16
#define Ss   1024
#define Ee   1024
#define HD   64
#define NROWS (Bsz*Ss)   // 2048
#define BH   (Bsz*Hh)    // 32

#define XSTRIDE (NROWS*Ee)   // 2097152
#define WSTRIDE (Ee*Ee)      // 1048576

// Scratch (device globals; no allocation allowed)
__device__ float g_Qt[BH*HD*Ss];   // [bh][d][s]
__device__ float g_Kt[BH*HD*Ss];   // [bh][d][s]
__device__ float g_V [NROWS*Ee];   // [n][e]
__device__ float g_A [NROWS*Ee];   // attention out [n][e]
__device__ float g_C1[NROWS*Ee];   // Q correction scores (natural)
__device__ float g_C2[NROWS*Ee];   // K correction scores (natural)

// bf16 split planes
__device__ __nv_bfloat16 g_X3[3*XSTRIDE];    // x: 3 planes (planes 0,1 also feed V GEMM)
__device__ __nv_bfloat16 g_A2[2*XSTRIDE];
__device__ __nv_bfloat16 g_Wq3[3*WSTRIDE];
__device__ __nv_bfloat16 g_Wk3[3*WSTRIDE];
__device__ __nv_bfloat16 g_Wv2[2*WSTRIDE];
__device__ __nv_bfloat16 g_Wo2[2*WSTRIDE];

// ---------------------------------------------------------------------------
// helpers
// ---------------------------------------------------------------------------
__device__ __forceinline__ uint32_t smem_to_u32(const void* p) {
    uint32_t a;
    asm("{ .reg .u64 t; cvta.to.shared.u64 t, %1; cvt.u32.u64 %0, t; }"
        : "=r"(a) : "l"(p));
    return a;
}
__device__ __forceinline__ u64 ffma2(u64 a, u64 b, u64 c) {
    u64 d;
    asm("fma.rn.f32x2 %0, %1, %2, %3;" : "=l"(d) : "l"(a), "l"(b), "l"(c));
    return d;
}
__device__ __forceinline__ u64 dup2(float x) {
    u64 d;
    asm("mov.b64 %0, {%1, %1};" : "=l"(d) : "f"(x));
    return d;
}
__device__ __forceinline__ void cpasync16(uint32_t s, const void* g) {
    asm volatile("cp.async.cg.shared.global [%0], [%1], 16;" :: "r"(s), "l"(g));
}
__device__ __forceinline__ void cpcommit() {
    asm volatile("cp.async.commit_group;" ::: "memory");
}
__device__ __forceinline__ void ldmx4(uint32_t* r, uint32_t addr) {
    asm volatile("ldmatrix.sync.aligned.m8n8.x4.shared.b16 {%0,%1,%2,%3}, [%4];"
                 : "=r"(r[0]), "=r"(r[1]), "=r"(r[2]), "=r"(r[3]) : "r"(addr));
}
__device__ __forceinline__ void mma16816(float* d, const uint32_t* a,
                                         uint32_t b0, uint32_t b1) {
    asm volatile("mma.sync.aligned.m16n8k16.row.col.f32.bf16.bf16.f32 "
                 "{%0,%1,%2,%3}, {%4,%5,%6,%7}, {%8,%9}, {%0,%1,%2,%3};"
                 : "+f"(d[0]), "+f"(d[1]), "+f"(d[2]), "+f"(d[3])
                 : "r"(a[0]), "r"(a[1]), "r"(a[2]), "r"(a[3]), "r"(b0), "r"(b1));
}

// ---------------------------------------------------------------------------
// fp32 -> bf16 plane converters (exact residual splits)
// ---------------------------------------------------------------------------
__global__ __launch_bounds__(256)
void conv2k(const float* __restrict__ src, __nv_bfloat16* __restrict__ dst,
            int n4, int pstride)
{
    int i = blockIdx.x * 256 + threadIdx.x;
    if (i >= n4) return;
    float4 a = ((const float4*)src)[i];
    float av[4] = {a.x, a.y, a.z, a.w};
    unsigned short p0[4], p1[4];
#pragma unroll
    for (int j = 0; j < 4; j++) {
        float x = av[j];
        __nv_bfloat16 h0 = __float2bfloat16(x);
        float r1 = x - __bfloat162float(h0);
        __nv_bfloat16 h1 = __float2bfloat16(r1);
        p0[j] = __bfloat16_as_ushort(h0);
        p1[j] = __bfloat16_as_ushort(h1);
    }
    ((uint2*)(dst))[i]           = *(uint2*)p0;
    ((uint2*)(dst + pstride))[i] = *(uint2*)p1;
}

__global__ __launch_bounds__(256)
void conv3k(const float* __restrict__ src, __nv_bfloat16* __restrict__ dst,
            int n4, int pstride)
{
    int i = blockIdx.x * 256 + threadIdx.x;
    if (i >= n4) return;
    float4 a = ((const float4*)src)[i];
    float av[4] = {a.x, a.y, a.z, a.w};
    unsigned short p0[4], p1[4], p2[4];
#pragma unroll
    for (int j = 0; j < 4; j++) {
        float x = av[j];
        __nv_bfloat16 h0 = __float2bfloat16(x);
        float r1 = x - __bfloat162float(h0);
        __nv_bfloat16 h1 = __float2bfloat16(r1);
        float r2 = r1 - __bfloat162float(h1);
        __nv_bfloat16 h2 = __float2bfloat16(r2);
        p0[j] = __bfloat16_as_ushort(h0);
        p1[j] = __bfloat16_as_ushort(h1);
        p2[j] = __bfloat16_as_ushort(h2);
    }
    ((uint2*)(dst))[i]               = *(uint2*)p0;
    ((uint2*)(dst + pstride))[i]     = *(uint2*)p1;
    ((uint2*)(dst + 2 * pstride))[i] = *(uint2*)p2;
}

// ---------------------------------------------------------------------------
// bf16x2 (3-pass) HMMA GEMM for V and O (proven R10): C = X @ W^T + bias.
// ---------------------------------------------------------------------------
#define PLB3  20480
#define BUFB3 40960
#define SMEM_HMMA (2*BUFB3)    // 81920

__global__ __launch_bounds__(256, 1)
void gemm_hmma3(const __nv_bfloat16* __restrict__ A2, int aStride,
                const __nv_bfloat16* __restrict__ W2,
                const float* __restrict__ bias, float* __restrict__ C)
{
    extern __shared__ __align__(16) char smem[];
    const uint32_t sb = smem_to_u32(smem);

    const int t    = threadIdx.x;
    const int wid  = t >> 5;
    const int lane = t & 31;

    const int m0 = blockIdx.x * 128;
    const int n0 = blockIdx.y * 128;

    const __nv_bfloat16* gA[4];
    const __nv_bfloat16* gB[4];
    uint32_t sAo[4];
#pragma unroll
    for (int u = 0; u < 4; u++) {
        int idx = t + (u << 8);
        int p   = idx >> 9;
        int rem = idx & 511;
        int r   = rem >> 2;
        int c8  = rem & 3;
        gA[u] = A2 + (size_t)p * aStride + (size_t)(m0 + r) * 1024 + c8 * 8;
        gB[u] = W2 + (size_t)p * WSTRIDE + (size_t)(n0 + r) * 1024 + c8 * 8;
        sAo[u] = (uint32_t)(p * 10240 + r * 80 + c8 * 16);
    }

    auto loadbuf = [&](int bb, int kc) {
        uint32_t base = sb + bb * BUFB3;
#pragma unroll
        for (int u = 0; u < 4; u++) cpasync16(base + sAo[u], gA[u] + kc * 32);
#pragma unroll
        for (int u = 0; u < 4; u++) cpasync16(base + PLB3 + sAo[u], gB[u] + kc * 32);
        cpcommit();
    };

    const int wm32 = (wid >> 1) * 32;
    const int wn64 = (wid & 1) * 64;
    const int arow = lane & 15;
    const uint32_t c8b = ((lane >> 4) & 1) * 16;

    float acc[2][8][4];
#pragma unroll
    for (int i = 0; i < 2; i++)
#pragma unroll
        for (int j = 0; j < 8; j++)
#pragma unroll
            for (int q = 0; q < 4; q++) acc[i][j][q] = 0.0f;

    loadbuf(0, 0);

#pragma unroll 1
    for (int kc = 0; kc < 32; kc++) {
        if (kc < 31) {
            loadbuf((kc + 1) & 1, kc + 1);
            asm volatile("cp.async.wait_group 1;" ::: "memory");
        } else {
            asm volatile("cp.async.wait_group 0;" ::: "memory");
        }
        __syncthreads();

        const uint32_t bufo = sb + (kc & 1) * BUFB3;
#pragma unroll
        for (int ks = 0; ks < 2; ks++) {
            uint32_t aF[2][2][4];
            uint32_t bF[2][4][4];
#pragma unroll
            for (int p = 0; p < 2; p++)
#pragma unroll
                for (int mt = 0; mt < 2; mt++) {
                    uint32_t ad = bufo + p * 10240 +
                        (uint32_t)(wm32 + mt * 16 + arow) * 80 + ks * 32 + c8b;
                    ldmx4(aF[p][mt], ad);
                }
#pragma unroll
            for (int q = 0; q < 2; q++)
#pragma unroll
                for (int ng = 0; ng < 4; ng++) {
                    uint32_t bd = bufo + PLB3 + q * 10240 +
                        (uint32_t)(wn64 + ng * 16 + arow) * 80 + ks * 32 + c8b;
                    ldmx4(bF[q][ng], bd);
                }
#pragma unroll
            for (int i3 = 0; i3 < 3; i3++) {
                const int p = (i3 == 2) ? 1 : 0;
                const int q = (i3 == 1) ? 1 : 0;
#pragma unroll
                for (int mt = 0; mt < 2; mt++)
#pragma unroll
                    for (int nt = 0; nt < 8; nt++) {
                        const int ng = nt >> 1, par = nt & 1;
                        mma16816(acc[mt][nt], aF[p][mt],
                                 bF[q][ng][par], bF[q][ng][par + 2]);
                    }
            }
        }
        __syncthreads();
    }

    const int rbase = m0 + wm32 + (lane >> 2);
    const int cbase = n0 + wn64 + (lane & 3) * 2;
#pragma unroll
    for (int mt = 0; mt < 2; mt++) {
        const int r0 = rbase + mt * 16;
        const int r1 = r0 + 8;
#pragma unroll
        for (int nt = 0; nt < 8; nt++) {
            const int col = cbase + nt * 8;
            const float2 bi = *(const float2*)&bias[col];
            *(float2*)&C[(size_t)r0 * 1024 + col] =
                make_float2(acc[mt][nt][0] + bi.x, acc[mt][nt][1] + bi.y);
            *(float2*)&C[(size_t)r1 * 1024 + col] =
                make_float2(acc[mt][nt][2] + bi.x, acc[mt][nt][3] + bi.y);
        }
    }
}

// ---------------------------------------------------------------------------
// Correction GEMM: Scorr = sum over passes (0,1),(1,0),(1,1),(0,2),(2,0)
// of Xp @ Wq^T, plus bias. Natural fp32 output. 3 planes in smem.
// ---------------------------------------------------------------------------
#define PLBC  30720
#define BUFBC 61440
#define SMEM_CORR (2*BUFBC)    // 122880

__global__ __launch_bounds__(256, 1)
void gemm_corr5(const __nv_bfloat16* __restrict__ A3,
                const __nv_bfloat16* __restrict__ W3a, const float* __restrict__ Ba, float* __restrict__ Ca,
                const __nv_bfloat16* __restrict__ W3b, const float* __restrict__ Bb, float* __restrict__ Cb)
{
    extern __shared__ __align__(16) char smem[];
    const uint32_t sb = smem_to_u32(smem);

    const int t    = threadIdx.x;
    const int wid  = t >> 5;
    const int lane = t & 31;

    const int z = blockIdx.z;
    const __nv_bfloat16* W3 = z ? W3b : W3a;
    const float* bias = z ? Bb : Ba;
    float*       C    = z ? Cb : Ca;

    const int m0 = blockIdx.x * 128;
    const int n0 = blockIdx.y * 128;

    const __nv_bfloat16* gA[6];
    const __nv_bfloat16* gB[6];
    uint32_t sAo[6];
#pragma unroll
    for (int u = 0; u < 6; u++) {
        int idx = t + (u << 8);            // 0..1535
        int p   = idx >> 9;                // plane 0..2
        int rem = idx & 511;
        int r   = rem >> 2;
        int c8  = rem & 3;
        gA[u] = A3 + (size_t)p * XSTRIDE + (size_t)(m0 + r) * 1024 + c8 * 8;
        gB[u] = W3 + (size_t)p * WSTRIDE + (size_t)(n0 + r) * 1024 + c8 * 8;
        sAo[u] = (uint32_t)(p * 10240 + r * 80 + c8 * 16);
    }

    auto loadbuf = [&](int bb, int kc) {
        uint32_t base = sb + bb * BUFBC;
#pragma unroll
        for (int u = 0; u < 6; u++) cpasync16(base + sAo[u], gA[u] + kc * 32);
#pragma unroll
        for (int u = 0; u < 6; u++) cpasync16(base + PLBC + sAo[u], gB[u] + kc * 32);
        cpcommit();
    };

    const int wm32 = (wid >> 1) * 32;
    const int wn64 = (wid & 1) * 64;
    const int arow = lane & 15;
    const uint32_t c8b = ((lane >> 4) & 1) * 16;

    float acc[2][8][4];
#pragma unroll
    for (int i = 0; i < 2; i++)
#pragma unroll
        for (int j = 0; j < 8; j++)
#pragma unroll
            for (int q = 0; q < 4; q++) acc[i][j][q] = 0.0f;

    loadbuf(0, 0);

#pragma unroll 1
    for (int kc = 0; kc < 32; kc++) {
        if (kc < 31) {
            loadbuf((kc + 1) & 1, kc + 1);
            asm volatile("cp.async.wait_group 1;" ::: "memory");
        } else {
            asm volatile("cp.async.wait_group 0;" ::: "memory");
        }
        __syncthreads();

        const uint32_t bufo = sb + (kc & 1) * BUFBC;
#pragma unroll
        for (int ks = 0; ks < 2; ks++) {
            uint32_t aF[3][2][4];
            uint32_t bF[3][4][4];
#pragma unroll
            for (int p = 0; p < 3; p++)
#pragma unroll
                for (int mt = 0; mt < 2; mt++) {
                    uint32_t ad = bufo + p * 10240 +
                        (uint32_t)(wm32 + mt * 16 + arow) * 80 + ks * 32 + c8b;
                    ldmx4(aF[p][mt], ad);
                }
#pragma unroll
            for (int q = 0; q < 3; q++)
#pragma unroll
                for (int ng = 0; ng < 4; ng++) {
                    uint32_t bd = bufo + PLBC + q * 10240 +
                        (uint32_t)(wn64 + ng * 16 + arow) * 80 + ks * 32 + c8b;
                    ldmx4(bF[q][ng], bd);
                }
            // passes (p,q): (0,1),(1,0),(1,1),(0,2),(2,0)
            const int P5[5] = {0, 1, 1, 0, 2};
            const int Q5[5] = {1, 0, 1, 2, 0};
#pragma unroll
            for (int i5 = 0; i5 < 5; i5++) {
                const int p = P5[i5], q = Q5[i5];
#pragma unroll
                for (int mt = 0; mt < 2; mt++)
#pragma unroll
                    for (int nt = 0; nt < 8; nt++) {
                        const int ng = nt >> 1, par = nt & 1;
                        mma16816(acc[mt][nt], aF[p][mt],
                                 bF[q][ng][par], bF[q][ng][par + 2]);
                    }
            }
        }
        __syncthreads();
    }

    const int rbase = m0 + wm32 + (lane >> 2);
    const int cbase = n0 + wn64 + (lane & 3) * 2;
#pragma unroll
    for (int mt = 0; mt < 2; mt++) {
        const int r0 = rbase + mt * 16;
        const int r1 = r0 + 8;
#pragma unroll
        for (int nt = 0; nt < 8; nt++) {
            const int col = cbase + nt * 8;
            const float2 bi = *(const float2*)&bias[col];
            *(float2*)&C[(size_t)r0 * 1024 + col] =
                make_float2(acc[mt][nt][0] + bi.x, acc[mt][nt][1] + bi.y);
            *(float2*)&C[(size_t)r1 * 1024 + col] =
                make_float2(acc[mt][nt][2] + bi.x, acc[mt][nt][3] + bi.y);
        }
    }
}

// ---------------------------------------------------------------------------
// Main-pass GEMM: plane0 @ plane0^T with TWO k-segment accumulators
// (kc<16 / kc>=16) to minimize HMMA truncation bias. Epilogue adds the
// precomputed correction (Scorr+bias) and stores head-transposed.
// ---------------------------------------------------------------------------
#define PLB1  10240
#define BUFB1 20480
#define SMEM_MAIN (2*BUFB1)    // 40960

__global__ __launch_bounds__(256, 1)
void gemm_main1(const __nv_bfloat16* __restrict__ A0,
                const __nv_bfloat16* __restrict__ W0a, const float* __restrict__ Ra, float* __restrict__ Ca,
                const __nv_bfloat16* __restrict__ W0b, const float* __restrict__ Rb, float* __restrict__ Cb)
{
    extern __shared__ __align__(16) char smem[];
    const uint32_t sb = smem_to_u32(smem);

    const int t    = threadIdx.x;
    const int wid  = t >> 5;
    const int lane = t & 31;

    const int z = blockIdx.z;
    const __nv_bfloat16* W0 = z ? W0b : W0a;
    const float* R = z ? Rb : Ra;       // correction scores (+bias), natural
    float*       C = z ? Cb : Ca;       // head-transposed destination

    const int m0 = blockIdx.x * 128;
    const int n0 = blockIdx.y * 128;

    const __nv_bfloat16* gA[2];
    const __nv_bfloat16* gB[2];
    uint32_t sAo[2];
#pragma unroll
    for (int u = 0; u < 2; u++) {
        int idx = t + (u << 8);            // 0..511
        int r   = idx >> 2;
        int c8  = idx & 3;
        gA[u] = A0 + (size_t)(m0 + r) * 1024 + c8 * 8;
        gB[u] = W0 + (size_t)(n0 + r) * 1024 + c8 * 8;
        sAo[u] = (uint32_t)(r * 80 + c8 * 16);
    }

    auto loadbuf = [&](int bb, int kc) {
        uint32_t base = sb + bb * BUFB1;
        cpasync16(base + sAo[0], gA[0] + kc * 32);
        cpasync16(base + sAo[1], gA[1] + kc * 32);
        cpasync16(base + PLB1 + sAo[0], gB[0] + kc * 32);
        cpasync16(base + PLB1 + sAo[1], gB[1] + kc * 32);
        cpcommit();
    };

    const int wm32 = (wid >> 1) * 32;
    const int wn64 = (wid & 1) * 64;
    const int arow = lane & 15;
    const uint32_t c8b = ((lane >> 4) & 1) * 16;

    float accA[2][8][4], accB[2][8][4];
#pragma unroll
    for (int i = 0; i < 2; i++)
#pragma unroll
        for (int j = 0; j < 8; j++)
#pragma unroll
            for (int q = 0; q < 4; q++) { accA[i][j][q] = 0.0f; accB[i][j][q] = 0.0f; }

    loadbuf(0, 0);

#pragma unroll 1
    for (int kc = 0; kc < 32; kc++) {
        if (kc < 31) {
            loadbuf((kc + 1) & 1, kc + 1);
            asm volatile("cp.async.wait_group 1;" ::: "memory");
        } else {
            asm volatile("cp.async.wait_group 0;" ::: "memory");
        }
        __syncthreads();

        const uint32_t bufo = sb + (kc & 1) * BUFB1;
#pragma unroll
        for (int ks = 0; ks < 2; ks++) {
            uint32_t aF[2][4];
            uint32_t bF[4][4];
#pragma unroll
            for (int mt = 0; mt < 2; mt++) {
                uint32_t ad = bufo +
                    (uint32_t)(wm32 + mt * 16 + arow) * 80 + ks * 32 + c8b;
                ldmx4(aF[mt], ad);
            }
#pragma unroll
            for (int ng = 0; ng < 4; ng++) {
                uint32_t bd = bufo + PLB1 +
                    (uint32_t)(wn64 + ng * 16 + arow) * 80 + ks * 32 + c8b;
                ldmx4(bF[ng], bd);
            }
            if (kc < 16) {
#pragma unroll
                for (int mt = 0; mt < 2; mt++)
#pragma unroll
                    for (int nt = 0; nt < 8; nt++) {
                        const int ng = nt >> 1, par = nt & 1;
                        mma16816(accA[mt][nt], aF[mt], bF[ng][par], bF[ng][par + 2]);
                    }
            } else {
#pragma unroll
                for (int mt = 0; mt < 2; mt++)
#pragma unroll
                    for (int nt = 0; nt < 8; nt++) {
                        const int ng = nt >> 1, par = nt & 1;
                        mma16816(accB[mt][nt], aF[mt], bF[ng][par], bF[ng][par + 2]);
                    }
            }
        }
        __syncthreads();
    }

    // epilogue: (segA + segB) + correction, head-transposed store
    const int rbase = m0 + wm32 + (lane >> 2);
    const int cbase = n0 + wn64 + (lane & 3) * 2;
#pragma unroll
    for (int mt = 0; mt < 2; mt++) {
        const int r0 = rbase + mt * 16;
        const int r1 = r0 + 8;
#pragma unroll
        for (int nt = 0; nt < 8; nt++) {
            const int col = cbase + nt * 8;        // even -> d even, d+1 same head
            const float2 c0 = *(const float2*)&R[(size_t)r0 * 1024 + col];
            const float2 c1 = *(const float2*)&R[(size_t)r1 * 1024 + col];
            const float d00 = (accA[mt][nt][0] + accB[mt][nt][0]) + c0.x;
            const float d01 = (accA[mt][nt][1] + accB[mt][nt][1]) + c0.y;
            const float d10 = (accA[mt][nt][2] + accB[mt][nt][2]) + c1.x;
            const float d11 = (accA[mt][nt][3] + accB[mt][nt][3]) + c1.y;
            const int h = col >> 6, d = col & 63;
            {
                const int bb = r0 >> 10, s = r0 & 1023;
                C[((size_t)((bb << 4) | h) * 64 + d)     * 1024 + s] = d00;
                C[((size_t)((bb << 4) | h) * 64 + d + 1) * 1024 + s] = d01;
            }
            {
                const int bb = r1 >> 10, s = r1 & 1023;
                C[((size_t)((bb << 4) | h) * 64 + d)     * 1024 + s] = d10;
                C[((size_t)((bb << 4) | h) * 64 + d + 1) * 1024 + s] = d11;
            }
        }
    }
}

// ----------------------------------------------------------------------------
// Fused scores + exact top-64 + softmax + A@V (R5-exact, unchanged).
// ----------------------------------------------------------------------------
__global__ __launch_bounds__(512, 1)
void attn_kernel(const float* __restrict__ Qt, const float* __restrict__ Kt,
                 const float* __restrict__ V,  float* __restrict__ A)
{
    extern __shared__ __align__(16) float sm[];
    float* ks   = sm;                      // [64][256]
    float* qs   = sm + 16384;              // [64][32]
    float* sc   = sm + 18432;              // [32][1024]
    float* wsh  = sm + 51200;              // [16][64]
    int*   sidx = (int*)(sm + 52224);      // [16][64]

    const int t   = threadIdx.x;
    const int blk = blockIdx.x;
    const int bh  = blk >> 5;
    const int q0g = (blk & 31) << 5;
    const int bb  = bh >> 4;
    const int hh  = bh & 15;

    for (int i = t; i < 2048; i += 512) {
        int d = i >> 5, qi = i & 31;
        qs[i] = Qt[((size_t)bh*64 + d)*1024 + q0g + qi];
    }

    const int qt = t >> 6;
    const int q0 = qt * 4;
    const int k0 = (t & 63) * 4;
    const int rr = t >> 6;
    const int s4 = (t & 63) * 4;

    for (int c = 0; c < 4; c++) {
        __syncthreads();
#pragma unroll
        for (int p = 0; p < 8; p++) {
            int r = p*8 + rr;
            *(float4*)&ks[r*256 + s4] =
                *(const float4*)&Kt[((size_t)bh*64 + r)*1024 + c*256 + s4];
        }
        __syncthreads();

        u64 acc2[4][2];
#pragma unroll
        for (int i = 0; i < 4; i++) { acc2[i][0] = 0ull; acc2[i][1] = 0ull; }

#pragma unroll 4
        for (int d = 0; d < 64; d++) {
            float4 qv = *(const float4*)&qs[d*32 + q0];
            ulonglong2 kv = *(const ulonglong2*)&ks[d*256 + k0];
            u64 a0 = dup2(qv.x), a1 = dup2(qv.y), a2 = dup2(qv.z), a3 = dup2(qv.w);
            acc2[0][0] = ffma2(a0, kv.x, acc2[0][0]);
            acc2[0][1] = ffma2(a0, kv.y, acc2[0][1]);
            acc2[1][0] = ffma2(a1, kv.x, acc2[1][0]);
            acc2[1][1] = ffma2(a1, kv.y, acc2[1][1]);
            acc2[2][0] = ffma2(a2, kv.x, acc2[2][0]);
            acc2[2][1] = ffma2(a2, kv.y, acc2[2][1]);
            acc2[3][0] = ffma2(a3, kv.x, acc2[3][0]);
            acc2[3][1] = ffma2(a3, kv.y, acc2[3][1]);
        }
#pragma unroll
        for (int i = 0; i < 4; i++) {
            union { u64 u; float2 f; } c0, c1;
            c0.u = acc2[i][0]; c1.u = acc2[i][1];
            float4 v = {c0.f.x*0.125f, c0.f.y*0.125f, c1.f.x*0.125f, c1.f.y*0.125f};
            *(float4*)&sc[(q0+i)*1024 + (c<<8) + k0] = v;
        }
    }
    __syncthreads();

    const int w    = t >> 5;
    const int lane = t & 31;
    const unsigned lmlt = (1u << lane) - 1u;

    for (int qq = 0; qq < 2; qq++) {
        const int q = 2*w + qq;

        unsigned mv[32];
        unsigned mn = 0xFFFFFFFFu, mx = 0u;
#pragma unroll
        for (int j = 0; j < 32; j++) {
            unsigned u = __float_as_uint(sc[q*1024 + j*32 + lane]);
            unsigned m = (u & 0x80000000u) ? ~u : (u | 0x80000000u);
            mv[j] = m;
            mn = min(mn, m); mx = max(mx, m);
        }
        mn = __reduce_min_sync(0xFFFFFFFFu, mn);
        mx = __reduce_max_sync(0xFFFFFFFFu, mx);

        unsigned lo = mn, hi = mx, thr = 0u;
        bool exact = false;
        while (hi - lo > 1u) {
            unsigned mid = lo + ((hi - lo) >> 1);
            int cgt = 0;
#pragma unroll
            for (int j = 0; j < 32; j++) cgt += (mv[j] > mid);
            cgt = __reduce_add_sync(0xFFFFFFFFu, cgt);
            if (cgt == 64) { thr = mid; exact = true; break; }
            if (cgt > 64) lo = mid; else hi = mid;
        }

        if (exact) {
            int nsel = 0;
#pragma unroll
            for (int j = 0; j < 32; j++) {
                bool p = mv[j] > thr;
                unsigned bal = __ballot_sync(0xFFFFFFFFu, p);
                if (p) sidx[w*64 + nsel + __popc(bal & lmlt)] = j*32 + lane;
                nsel += __popc(bal);
            }
        } else {
            unsigned t2 = hi;
            int nsel = 0;
#pragma unroll
            for (int j = 0; j < 32; j++) {
                bool p = mv[j] > t2;
                unsigned bal = __ballot_sync(0xFFFFFFFFu, p);
                if (p) sidx[w*64 + nsel + __popc(bal & lmlt)] = j*32 + lane;
                nsel += __popc(bal);
            }
#pragma unroll
            for (int j = 0; j < 32; j++) {
                bool p = (mv[j] == t2);
                unsigned bal = __ballot_sync(0xFFFFFFFFu, p);
                if (p) {
                    int pos = nsel + __popc(bal & lmlt);
                    if (pos < 64) sidx[w*64 + pos] = j*32 + lane;
                }
                nsel += __popc(bal);
            }
        }
        __syncwarp();

        int  i0 = sidx[w*64 + lane];
        int  i1 = sidx[w*64 + lane + 32];
        float v0 = sc[q*1024 + i0];
        float v1 = sc[q*1024 + i1];
        float mxf = fmaxf(v0, v1);
#pragma unroll
        for (int o = 16; o > 0; o >>= 1) mxf = fmaxf(mxf, __shfl_xor_sync(0xFFFFFFFFu, mxf, o));
        float e0 = __expf(v0 - mxf), e1 = __expf(v1 - mxf);
        float ssum = e0 + e1;
#pragma unroll
        for (int o = 16; o > 0; o >>= 1) ssum += __shfl_xor_sync(0xFFFFFFFFu, ssum, o);
        wsh[w*64 + lane]      = e0;
        wsh[w*64 + lane + 32] = e1;
        __syncwarp();

        float ax = 0.0f, ay = 0.0f;
        const int d0 = 2*lane;
        const size_t vbase = ((size_t)bb * 1024) * 1024 + hh*64 + d0;
#pragma unroll 4
        for (int j2 = 0; j2 < 64; j2++) {
            int   id = sidx[w*64 + j2];
            float wj = wsh[w*64 + j2];
            float2 vv = *(const float2*)&V[vbase + (size_t)id*1024];
            ax += wj * vv.x;
            ay += wj * vv.y;
        }
        float invs = 1.0f / ssum;
        float2 outv; outv.x = ax*invs; outv.y = ay*invs;
        int qg = q0g + q;
        *(float2*)&A[((size_t)bb*1024 + qg)*1024 + hh*64 + d0] = outv;
        __syncwarp();
    }
}

// ----------------------------------------------------------------------------
extern "C" void kernel_launch(void* const* d_in, const int* in_sizes, int n_in,
                              void* d_out, int out_size)
{
    const float* x  = (const float*)d_in[0];
    const float* Wq = (const float*)d_in[1];
    const float* bq = (const float*)d_in[2];
    const float* Wk = (const float*)d_in[3];
    const float* bk = (const float*)d_in[4];
    const float* Wv = (const float*)d_in[5];
    const float* bv = (const float*)d_in[6];
    const float* Wo = (const float*)d_in[7];
    const float* bo = (const float*)d_in[8];
    float* out = (float*)d_out;

    float *Qt, *Kt, *Vv, *Aa, *C1, *C2;
    cudaGetSymbolAddress((void**)&Qt, g_Qt);
    cudaGetSymbolAddress((void**)&Kt, g_Kt);
    cudaGetSymbolAddress((void**)&Vv, g_V);
    cudaGetSymbolAddress((void**)&Aa, g_A);
    cudaGetSymbolAddress((void**)&C1, g_C1);
    cudaGetSymbolAddress((void**)&C2, g_C2);
    __nv_bfloat16 *X3, *A2, *Wq3, *Wk3, *Wv2, *Wo2;
    cudaGetSymbolAddress((void**)&X3,  g_X3);
    cudaGetSymbolAddress((void**)&A2,  g_A2);
    cudaGetSymbolAddress((void**)&Wq3, g_Wq3);
    cudaGetSymbolAddress((void**)&Wk3, g_Wk3);
    cudaGetSymbolAddress((void**)&Wv2, g_Wv2);
    cudaGetSymbolAddress((void**)&Wo2, g_Wo2);

    const int SMEM_ATTN = 53248 * 4;
    cudaFuncSetAttribute(attn_kernel,
                         cudaFuncAttributeMaxDynamicSharedMemorySize, SMEM_ATTN);
    cudaFuncSetAttribute(gemm_hmma3,
                         cudaFuncAttributeMaxDynamicSharedMemorySize, SMEM_HMMA);
    cudaFuncSetAttribute(gemm_corr5,
                         cudaFuncAttributeMaxDynamicSharedMemorySize, SMEM_CORR);
    cudaFuncSetAttribute(gemm_main1,
                         cudaFuncAttributeMaxDynamicSharedMemorySize, SMEM_MAIN);

    // plane conversions
    conv3k<<<XSTRIDE/4/256, 256>>>(x,  X3,  XSTRIDE/4, XSTRIDE);
    conv3k<<<WSTRIDE/4/256, 256>>>(Wq, Wq3, WSTRIDE/4, WSTRIDE);
    conv3k<<<WSTRIDE/4/256, 256>>>(Wk, Wk3, WSTRIDE/4, WSTRIDE);
    conv2k<<<WSTRIDE/4/256, 256>>>(Wv, Wv2, WSTRIDE/4, WSTRIDE);
    conv2k<<<WSTRIDE/4/256, 256>>>(Wo, Wo2, WSTRIDE/4, WSTRIDE);

    // Q/K projections: correction passes, then main pass (+corr, transposed)
    dim3 gqk(NROWS/128, Ee/128, 2);
    gemm_corr5<<<gqk, 256, SMEM_CORR>>>(X3,
                                        Wq3, bq, C1,
                                        Wk3, bk, C2);
    gemm_main1<<<gqk, 256, SMEM_MAIN>>>(X3,
                                        Wq3, C1, Qt,
                                        Wk3, C2, Kt);

    // V: HMMA bf16x2 (uses X3 planes 0,1)
    dim3 gv(NROWS/128, Ee/128);
    gemm_hmma3<<<gv, 256, SMEM_HMMA>>>(X3, XSTRIDE, Wv2, bv, Vv);

    attn_kernel<<<BH*32, 512, SMEM_ATTN>>>(Qt, Kt, Vv, Aa);

    // O-projection: HMMA bf16x2
    conv2k<<<XSTRIDE/4/256, 256>>>(Aa, A2, XSTRIDE/4, XSTRIDE);
    gemm_hmma3<<<gv, 256, SMEM_HMMA>>>(A2, XSTRIDE, Wo2, bo, out);
}